// round 7
// baseline (speedup 1.0000x reference)
#include <cuda_runtime.h>

namespace {

constexpr int Wd  = 512;
constexpr int Hd  = 512;
constexpr int TH  = 16;           // output rows per CTA
constexpr int NT  = 256;
constexpr int WIN = TH + 14;      // 30-row input window
constexpr int VW1 = 532;          // vbuf row stride (words): 8 pad | 512 | 12 pad
constexpr int VW2 = 516;          // obuf row stride (words)
constexpr int SMEM_BYTES = (TH * VW1 + TH * VW2) * 4;   // 67072

__device__ __forceinline__ unsigned long long pack2(float lo, float hi) {
    unsigned long long r;
    asm("mov.b64 %0, {%1, %2};" : "=l"(r) : "f"(lo), "f"(hi));
    return r;
}
__device__ __forceinline__ void fma2(unsigned long long& d,
                                     unsigned long long a,
                                     unsigned long long b) {
    asm("fma.rn.f32x2 %0, %1, %2, %0;" : "+l"(d) : "l"(a), "l"(b));
}
__host__ __device__ constexpr int widx(int j) { return j < 8 ? j : 14 - j; }

__global__ void __launch_bounds__(NT, 3)
gauss_kernel(const float* __restrict__ x, const float* __restrict__ sigma,
             float* __restrict__ out, int C)
{
    extern __shared__ float smem[];
    float* vbuf = smem;              // [TH][VW1], data cols at word 8..519
    float* obuf = smem + TH * VW1;   // [TH][VW2]

    const int strip = blockIdx.x;
    const int ch    = blockIdx.y;
    const int b     = blockIdx.z;
    const int tid   = threadIdx.x;
    const int r0    = strip * TH;

    // ---- symmetric 1D Gaussian weights (8 distinct), packed broadcast ----
    const float sg  = sigma[b];
    const float inv = 1.0f / (2.0f * sg * sg + 1e-8f);
    float w[8];
    float s = 0.0f;
#pragma unroll
    for (int i = 0; i < 8; ++i) {
        const float a = (float)(7 - i);
        w[i] = __expf(-a * a * inv);
        s += (i < 7) ? 2.0f * w[i] : w[i];
    }
    const float rs = 1.0f / s;
    unsigned long long wp[8];
#pragma unroll
    for (int i = 0; i < 8; ++i) { w[i] *= rs; wp[i] = pack2(w[i], w[i]); }

    const size_t img = (size_t)(b * C + ch) * (Hd * Wd);
    const float* __restrict__ xp = x + img;
    float* __restrict__       op = out + img;

    // ---- zero vbuf pads: words [0,8) and [520,532) per row ----
    if (tid < 80) {
        const int row = tid / 5;
        const int q   = tid % 5;
        const int wd  = (q < 2) ? q * 4 : 520 + (q - 2) * 4;
        *reinterpret_cast<float4*>(&vbuf[row * VW1 + wd]) =
            make_float4(0.f, 0.f, 0.f, 0.f);
    }

    // ================= Stage 1: vertical, global -> vbuf =================
    // thread: 2 cols x 16 rows; 30-row sliding input window
    {
        const int c0 = tid * 2;
        const int rbase = r0 - 7;

        unsigned long long acc[TH];
#pragma unroll
        for (int o = 0; o < TH; ++o) acc[o] = 0ull;

        if (rbase >= 0 && rbase + WIN - 1 < Hd) {
            const float* p = xp + (size_t)rbase * Wd + c0;
#pragma unroll
            for (int rr = 0; rr < WIN; ++rr) {
                const unsigned long long v =
                    *reinterpret_cast<const unsigned long long*>(p + rr * Wd);
#pragma unroll
                for (int o = 0; o < TH; ++o) {
                    const int j = rr - o;
                    if (j >= 0 && j < 15) fma2(acc[o], v, wp[widx(j)]);
                }
            }
        } else {
            const float* colp = xp + c0;
#pragma unroll
            for (int rr = 0; rr < WIN; ++rr) {
                const int gr = rbase + rr;
                if ((unsigned)gr < (unsigned)Hd) {
                    const unsigned long long v =
                        *reinterpret_cast<const unsigned long long*>(
                            colp + (size_t)gr * Wd);
#pragma unroll
                    for (int o = 0; o < TH; ++o) {
                        const int j = rr - o;
                        if (j >= 0 && j < 15) fma2(acc[o], v, wp[widx(j)]);
                    }
                }
            }
        }
#pragma unroll
        for (int o = 0; o < TH; ++o)
            *reinterpret_cast<unsigned long long*>(&vbuf[o * VW1 + 8 + c0]) =
                acc[o];
    }
    __syncthreads();

    // ===== Stage 2: horizontal, vbuf -> obuf, sliding 32-col segment =====
    // thread: 1 row x 32 consecutive cols; rolling 20-float / 17-pair window
    {
        const int row = tid & 15;
        const int seg = tid >> 4;
        const float* rp = &vbuf[row * VW1 + 8 + seg * 32];  // col c0 = seg*32
        float* ob = &obuf[row * VW2 + seg * 32];

        // initial window: f[i] = col c0-8+i, i = 0..19
        float f[20];
#pragma unroll
        for (int k = 0; k < 5; ++k) {
            const float4 v = *reinterpret_cast<const float4*>(rp - 8 + 4 * k);
            f[4 * k + 0] = v.x; f[4 * k + 1] = v.y;
            f[4 * k + 2] = v.z; f[4 * k + 3] = v.w;
        }
        // rolling pairs: P[i] = (f[i+1], f[i+2])  (s = i+1 in 1..17)
        unsigned long long P[17];
#pragma unroll
        for (int i = 0; i < 17; ++i) P[i] = pack2(f[i + 1], f[i + 2]);
        float cA = f[18], cB = f[19];

#pragma unroll
        for (int c = 0; c < 8; ++c) {
            unsigned long long ap0 = 0ull, ap1 = 0ull;
#pragma unroll
            for (int i = 0; i < 17; ++i) {
                const int sidx = i + 1;
                if (sidx <= 15) fma2(ap0, P[i], wp[widx(sidx - 1)]);
                if (sidx >= 3)  fma2(ap1, P[i], wp[widx(sidx - 3)]);
            }
            *reinterpret_cast<ulonglong2*>(ob + 4 * c) =
                make_ulonglong2(ap0, ap1);

            if (c < 7) {
                const float4 nv =
                    *reinterpret_cast<const float4*>(rp + 12 + 4 * c);
#pragma unroll
                for (int i = 0; i < 13; ++i) P[i] = P[i + 4];
                P[13] = pack2(cA, cB);
                P[14] = pack2(cB, nv.x);
                P[15] = pack2(nv.x, nv.y);
                P[16] = pack2(nv.y, nv.z);
                cA = nv.z; cB = nv.w;
            }
        }
    }
    __syncthreads();

    // ================= Stage 3: coalesced copy obuf -> global =================
#pragma unroll
    for (int i = 0; i < 8; ++i) {
        const int idx = tid + i * NT;        // float4 index 0..2047
        const int row = idx >> 7;            // 128 float4s per row
        const int c4  = (idx & 127) * 4;
        const float4 v = *reinterpret_cast<const float4*>(&obuf[row * VW2 + c4]);
        *reinterpret_cast<float4*>(op + (size_t)(r0 + row) * Wd + c4) = v;
    }
}

}  // namespace

extern "C" void kernel_launch(void* const* d_in, const int* in_sizes, int n_in,
                              void* d_out, int out_size) {
    const float* x     = (const float*)d_in[0];
    const float* sigma = (const float*)d_in[1];
    float* out         = (float*)d_out;

    const int B = in_sizes[1];                      // 32
    const int C = in_sizes[0] / (B * Hd * Wd);      // 3

    cudaFuncSetAttribute(gauss_kernel,
                         cudaFuncAttributeMaxDynamicSharedMemorySize, SMEM_BYTES);

    dim3 grid(Hd / TH, C, B);                       // 32 x 3 x 32 = 3072
    gauss_kernel<<<grid, NT, SMEM_BYTES>>>(x, sigma, out, C);
}

// round 8
// speedup vs baseline: 1.2925x; 1.2925x over previous
#include <cuda_runtime.h>

namespace {

constexpr int Wd  = 512;
constexpr int Hd  = 512;
constexpr int TH  = 16;           // output rows per CTA
constexpr int VW  = 528;          // padded vbuf width (8 zero cols each side)
constexpr int NT  = 256;
constexpr int WIN = TH + 14;      // 30-row input window

__device__ __forceinline__ unsigned long long pack2(float lo, float hi) {
    unsigned long long r;
    asm("mov.b64 %0, {%1, %2};" : "=l"(r) : "f"(lo), "f"(hi));
    return r;
}
__device__ __forceinline__ void fma2(unsigned long long& d,
                                     unsigned long long a,
                                     unsigned long long b) {
    asm("fma.rn.f32x2 %0, %1, %2, %0;" : "+l"(d) : "l"(a), "l"(b));
}
__host__ __device__ constexpr int widx(int j) { return j < 8 ? j : 14 - j; }

union F4 {
    float4 f;
    unsigned long long u[2];
    float s[4];
};

__global__ void __launch_bounds__(NT, 4)
gauss_kernel(const float* __restrict__ x, const float* __restrict__ sigma,
             float* __restrict__ out, int C)
{
    __shared__ float vbuf[TH * VW];   // 33792 B -> 4 CTAs/SM

    const int strip = blockIdx.x;
    const int ch    = blockIdx.y;
    const int b     = blockIdx.z;
    const int tid   = threadIdx.x;
    const int r0    = strip * TH;

    // ---- symmetric 1D Gaussian weights (8 distinct), packed broadcast ----
    const float sg  = sigma[b];
    const float inv = 1.0f / (2.0f * sg * sg + 1e-8f);
    float w[8];
    float s = 0.0f;
#pragma unroll
    for (int i = 0; i < 8; ++i) {
        const float a = (float)(7 - i);
        w[i] = __expf(-a * a * inv);
        s += (i < 7) ? 2.0f * w[i] : w[i];
    }
    const float rs = 1.0f / s;
    unsigned long long wp[8];
#pragma unroll
    for (int i = 0; i < 8; ++i) { w[i] *= rs; wp[i] = pack2(w[i], w[i]); }

    const size_t img = (size_t)(b * C + ch) * (Hd * Wd);
    const float* __restrict__ xp = x + img;
    float* __restrict__       op = out + img;

    // ---- zero-fill column halos (words [0,8) and [520,528) per row) ----
    if (tid < 64) {
        const int row = tid >> 2;
        const int q   = tid & 3;
        const int cc  = (q < 2) ? q * 4 : 520 + (q - 2) * 4;
        *reinterpret_cast<float4*>(&vbuf[row * VW + cc]) =
            make_float4(0.f, 0.f, 0.f, 0.f);
    }

    // ================= Stage 1: vertical, global -> vbuf =================
    // thread: 2 cols x 16 rows; 30-row sliding input window
    {
        const int c0 = tid * 2;
        const int rbase = r0 - 7;

        unsigned long long acc[TH];
#pragma unroll
        for (int o = 0; o < TH; ++o) acc[o] = 0ull;

        if (rbase >= 0 && rbase + WIN - 1 < Hd) {
            const float* p = xp + (size_t)rbase * Wd + c0;
#pragma unroll
            for (int rr = 0; rr < WIN; ++rr) {
                const unsigned long long v =
                    *reinterpret_cast<const unsigned long long*>(p + rr * Wd);
#pragma unroll
                for (int o = 0; o < TH; ++o) {
                    const int j = rr - o;
                    if (j >= 0 && j < 15) fma2(acc[o], v, wp[widx(j)]);
                }
            }
        } else {
            const float* colp = xp + c0;
#pragma unroll
            for (int rr = 0; rr < WIN; ++rr) {
                const int gr = rbase + rr;
                if ((unsigned)gr < (unsigned)Hd) {
                    const unsigned long long v =
                        *reinterpret_cast<const unsigned long long*>(
                            colp + (size_t)gr * Wd);
#pragma unroll
                    for (int o = 0; o < TH; ++o) {
                        const int j = rr - o;
                        if (j >= 0 && j < 15) fma2(acc[o], v, wp[widx(j)]);
                    }
                }
            }
        }
#pragma unroll
        for (int o = 0; o < TH; ++o)
            *reinterpret_cast<unsigned long long*>(&vbuf[o * VW + 8 + c0]) =
                acc[o];
    }
    __syncthreads();

    // ================= Stage 2: horizontal, vbuf -> global =================
    // thread: 4-col chunk x 8 rows. Even-s input pairs come directly from
    // LDS.128 register pairs (no pack); only 9 odd-s pairs are packed.
    {
        const int chunk = tid & 127;
        const int rsel  = tid >> 7;
        const int gc0   = chunk * 4;
        const float* basep = &vbuf[8 + gc0];

#pragma unroll
        for (int t = 0; t < 8; ++t) {
            const int row = rsel + 2 * t;
            const float* rp = basep + row * VW;

            F4 v[5];
#pragma unroll
            for (int k = 0; k < 5; ++k)
                v[k].f = *reinterpret_cast<const float4*>(rp - 8 + 4 * k);

            // odd-s pairs O[k] = (f[2k+1], f[2k+2]), k = 0..8
            unsigned long long O[9];
#pragma unroll
            for (int k = 0; k < 9; ++k) {
                const int i0 = 2 * k + 1;
                const int i1 = 2 * k + 2;
                O[k] = pack2(v[i0 >> 2].s[i0 & 3], v[i1 >> 2].s[i1 & 3]);
            }

            unsigned long long ap0 = 0ull, ap1 = 0ull;
#pragma unroll
            for (int sidx = 1; sidx <= 17; ++sidx) {
                const unsigned long long P =
                    (sidx & 1) ? O[(sidx - 1) >> 1]
                               : v[sidx >> 2].u[(sidx >> 1) & 1];
                if (sidx <= 15) fma2(ap0, P, wp[widx(sidx - 1)]);
                if (sidx >= 3)  fma2(ap1, P, wp[widx(sidx - 3)]);
            }
            *reinterpret_cast<ulonglong2*>(op + (size_t)(r0 + row) * Wd + gc0) =
                make_ulonglong2(ap0, ap1);
        }
    }
}

}  // namespace

extern "C" void kernel_launch(void* const* d_in, const int* in_sizes, int n_in,
                              void* d_out, int out_size) {
    const float* x     = (const float*)d_in[0];
    const float* sigma = (const float*)d_in[1];
    float* out         = (float*)d_out;

    const int B = in_sizes[1];                      // 32
    const int C = in_sizes[0] / (B * Hd * Wd);      // 3

    dim3 grid(Hd / TH, C, B);                       // 32 x 3 x 32 = 3072
    gauss_kernel<<<grid, NT>>>(x, sigma, out, C);
}